// round 2
// baseline (speedup 1.0000x reference)
#include <cuda_runtime.h>
#include <cuda_bf16.h>
#include <cstddef>

// Problem shapes (fixed per reference setup_inputs):
//   idx:    [B, 2, N] f32,  B=16, N = 512*512 = 262144
//   source: [B, 640, 640, 3] f32
//   out:    [B, 512, 512, 3] f32
static constexpr int B_    = 16;
static constexpr int HS    = 640;
static constexpr int WS    = 640;
static constexpr int C_    = 3;
static constexpr int NPIX  = 512 * 512;            // 262144 per batch
static constexpr long long NTOT = (long long)B_ * NPIX;  // 4,194,304

// Each thread handles 4 consecutive pixels of one batch:
//  - 2x LDG.128 for the row/col index vectors (coalesced)
//  - up to 12 independent LDG.32 gathers (MLP ~12 hides latency)
//  - 3x STG.128 for the 48 output bytes (16B-aligned: group*48 % 16 == 0)
__global__ void __launch_bounds__(256) nn_gather_kernel(
    const float* __restrict__ idx,
    const float* __restrict__ src,
    float* __restrict__ out)
{
    long long g = (long long)blockIdx.x * blockDim.x + threadIdx.x;
    long long p0 = g * 4;                 // first pixel of this group
    if (p0 >= NTOT) return;

    int b = (int)(p0 / NPIX);
    int n = (int)(p0 - (long long)b * NPIX);   // NPIX % 4 == 0 -> group stays in one batch

    const float* idx_b = idx + (size_t)b * 2 * NPIX;
    float4 rows = *reinterpret_cast<const float4*>(idx_b + n);
    float4 cols = *reinterpret_cast<const float4*>(idx_b + NPIX + n);

    const float* sb = src + (size_t)b * HS * WS * C_;

    float rf[4] = {rows.x, rows.y, rows.z, rows.w};
    float cf[4] = {cols.x, cols.y, cols.z, cols.w};

    float v[12];
#pragma unroll
    for (int i = 0; i < 4; ++i) {
        // trunc(x + 0.5) toward zero, exactly like jnp.trunc(...).astype(int32)
        int ir = (int)(rf[i] + 0.5f);
        int ic = (int)(cf[i] + 0.5f);
        bool valid = (ir >= 0) & (ic >= 0) & (ir < HS) & (ic < WS);
        if (valid) {
            const float* p = sb + ((size_t)ir * WS + ic) * C_;
            v[i * 3 + 0] = __ldg(p + 0);
            v[i * 3 + 1] = __ldg(p + 1);
            v[i * 3 + 2] = __ldg(p + 2);
        } else {
            v[i * 3 + 0] = 0.0f;
            v[i * 3 + 1] = 0.0f;
            v[i * 3 + 2] = 0.0f;
        }
    }

    float4* o = reinterpret_cast<float4*>(out + (size_t)p0 * 3);
    o[0] = make_float4(v[0], v[1], v[2],  v[3]);
    o[1] = make_float4(v[4], v[5], v[6],  v[7]);
    o[2] = make_float4(v[8], v[9], v[10], v[11]);
}

extern "C" void kernel_launch(void* const* d_in, const int* in_sizes, int n_in,
                              void* d_out, int out_size)
{
    const float* idx = (const float*)d_in[0];   // [16, 2, 262144] f32
    const float* src = (const float*)d_in[1];   // [16, 640, 640, 3] f32
    float* out = (float*)d_out;                 // [16, 512, 512, 3] f32

    (void)in_sizes; (void)n_in; (void)out_size;

    const long long n_groups = NTOT / 4;        // 1,048,576
    const int threads = 256;
    const int blocks = (int)((n_groups + threads - 1) / threads);  // 4096
    nn_gather_kernel<<<blocks, threads>>>(idx, src, out);
}

// round 4
// speedup vs baseline: 1.4850x; 1.4850x over previous
#include <cuda_runtime.h>
#include <cuda_bf16.h>
#include <cstddef>

// Problem shapes (fixed per reference setup_inputs):
//   idx:    [B, 2, N] f32,  B=16, N = 512*512 = 262144
//   source: [B, 640, 640, 3] f32
//   out:    [B, 512, 512, 3] f32
static constexpr int B_    = 16;
static constexpr int HS    = 640;
static constexpr int WS    = 640;
static constexpr int C_    = 3;
static constexpr int NPIX  = 512 * 512;                  // 262144 per batch
static constexpr long long NTOT = (long long)B_ * NPIX;  // 4,194,304

// L1-wavefront-bound gather (R1 ncu: L1tex 76.4% = binding resource).
// Per pixel the 12 needed bytes start at element s = 3*q (only 4B-aligned).
// e = s & ~1 is 8B-aligned and [e, e+3] always covers [s, s+2], so TWO
// LDG.64 + parity selects replace THREE LDG.32: gather L1 wavefronts drop
// 3 -> 2 per pixel. Max touched element e+3 <= 1228797 < 640*640*3: in bounds.
__global__ void __launch_bounds__(256) nn_gather_kernel(
    const float* __restrict__ idx,
    const float* __restrict__ src,
    float* __restrict__ out)
{
    long long g = (long long)blockIdx.x * blockDim.x + threadIdx.x;
    long long p0 = g * 4;                 // first pixel of this group
    if (p0 >= NTOT) return;

    int b = (int)(p0 / NPIX);
    int n = (int)(p0 - (long long)b * NPIX);   // NPIX % 4 == 0 -> group stays in one batch

    const float* idx_b = idx + (size_t)b * 2 * NPIX;
    float4 rows = *reinterpret_cast<const float4*>(idx_b + n);
    float4 cols = *reinterpret_cast<const float4*>(idx_b + NPIX + n);

    const float* sb = src + (size_t)b * HS * WS * C_;

    float rf[4] = {rows.x, rows.y, rows.z, rows.w};
    float cf[4] = {cols.x, cols.y, cols.z, cols.w};

    float v[12];
#pragma unroll
    for (int i = 0; i < 4; ++i) {
        // trunc(x + 0.5) toward zero, exactly like jnp.trunc(...).astype(int32)
        int ir = (int)(rf[i] + 0.5f);
        int ic = (int)(cf[i] + 0.5f);
        bool valid = (ir >= 0) & (ic >= 0) & (ir < HS) & (ic < WS);
        float c0 = 0.0f, c1 = 0.0f, c2 = 0.0f;
        if (valid) {
            int s = (ir * WS + ic) * C_;       // 4B-aligned element index
            int e = s & ~1;                    // 8B-aligned; [e, e+3] covers [s, s+2]
            float2 A = *reinterpret_cast<const float2*>(sb + e);      // e, e+1
            float2 B = *reinterpret_cast<const float2*>(sb + e + 2);  // e+2, e+3
            bool odd = (s & 1) != 0;
            c0 = odd ? A.y : A.x;
            c1 = odd ? B.x : A.y;
            c2 = odd ? B.y : B.x;
        }
        v[i * 3 + 0] = c0;
        v[i * 3 + 1] = c1;
        v[i * 3 + 2] = c2;
    }

    float4* o = reinterpret_cast<float4*>(out + (size_t)p0 * 3);
    o[0] = make_float4(v[0], v[1], v[2],  v[3]);
    o[1] = make_float4(v[4], v[5], v[6],  v[7]);
    o[2] = make_float4(v[8], v[9], v[10], v[11]);
}

extern "C" void kernel_launch(void* const* d_in, const int* in_sizes, int n_in,
                              void* d_out, int out_size)
{
    const float* idx = (const float*)d_in[0];   // [16, 2, 262144] f32
    const float* src = (const float*)d_in[1];   // [16, 640, 640, 3] f32
    float* out = (float*)d_out;                 // [16, 512, 512, 3] f32

    (void)in_sizes; (void)n_in; (void)out_size;

    const long long n_groups = NTOT / 4;        // 1,048,576
    const int threads = 256;
    const int blocks = (int)((n_groups + threads - 1) / threads);  // 4096
    nn_gather_kernel<<<blocks, threads>>>(idx, src, out);
}